// round 12
// baseline (speedup 1.0000x reference)
#include <cuda_runtime.h>
#include <cuda_bf16.h>

// B=128, N=512, diagonals k=0..509 (offset k+1), len(k)=511-k.
// out = (loss[B], loss[B]).
//
// Quad scheme: aligned float4 at (row p, col 4m) has group j=4m-p (constant
// along p+=4); elements lie on diagonals k_e=j+e-1. Thread owns jA and
// jB=507-jA; warp lanes -> one contiguous 512B LDG.128 per row. Per-thread
// bounds (p <= 508-j). PHASE-SPLIT: side A fully processed and retired to
// smem before side B reuses the same 8 accumulator registers, freeing the
// register budget for an explicit 4-deep load batch (guaranteed MLP).
#define NN   512
#define KD   510
#define TPB  512
#define RSG  3           // 384 CTAs: single wave at 3/SM (proven geometry)
#define RST  6           // total row splits (RSG * 2 in-CTA)
#define STEP (4 * RST)   // 24 rows between a thread's consecutive quads
#define MAXB 256

__device__ float2 g_part[MAXB * RSG * 512];
__device__ int    g_count[MAXB];     // zero-init; reset by last CTA each replay

__global__ __launch_bounds__(TPB, 3)
void diag_quad(const float* __restrict__ S, float* __restrict__ out,
               int B, int out_size) {
    const int b    = blockIdx.x;
    const int rsg  = blockIdx.y;
    const int tid  = threadIdx.x;
    const int lane = tid & 31;
    const int w    = tid >> 5;       // 0..15
    const int rs   = w >> 3;         // in-CTA row split 0..1
    const int q    = w & 3;          // alignment class
    const int h    = (w >> 2) & 1;   // lane-half
    const int la   = h * 32 + lane;  // 0..63
    const int jA   = q - 2 + 4 * la;       // -2..253
    const int jB   = 509 - q - 4 * la;     // 509..254
    const int rst  = rsg * 2 + rs;         // 0..5

    const float* __restrict__ M = S + (size_t)b * NN * NN;

    __shared__ float psum[512][9];     // [slot][2e+stat]; stride 9 ⟂ 32 banks
    const int slotA = q + 4 * la;      // jA+2 : 0..255
    const int slotB = 511 - slotA;     // jB+2 : 256..511

    float s0, s1, s2, s3, t0, t1, t2, t3;

    // ================= Phase A: rows p ≡ (2-q) mod 4, cols p+jA =================
    s0 = s1 = s2 = s3 = t0 = t1 = t2 = t3 = 0.f;
    {
        int p = ((2 - q) & 3) + 4 * rst;
        const int pend = 508 - jA;                  // per-thread exact bound
        const float* ptr = M + (size_t)p * (NN + 1) + jA;
        const ptrdiff_t dstep = (ptrdiff_t)STEP * (NN + 1);
        // 4-deep explicit batch: 4 independent LDG.128 issued before any use.
        for (; p + 3 * STEP <= pend; p += 4 * STEP, ptr += 4 * dstep) {
            float4 x0 = __ldcs((const float4*)(ptr));
            float4 x1 = __ldcs((const float4*)(ptr + dstep));
            float4 x2 = __ldcs((const float4*)(ptr + 2 * dstep));
            float4 x3 = __ldcs((const float4*)(ptr + 3 * dstep));
            s0 += x0.x; t0 = fmaf(x0.x, x0.x, t0);
            s1 += x0.y; t1 = fmaf(x0.y, x0.y, t1);
            s2 += x0.z; t2 = fmaf(x0.z, x0.z, t2);
            s3 += x0.w; t3 = fmaf(x0.w, x0.w, t3);
            s0 += x1.x; t0 = fmaf(x1.x, x1.x, t0);
            s1 += x1.y; t1 = fmaf(x1.y, x1.y, t1);
            s2 += x1.z; t2 = fmaf(x1.z, x1.z, t2);
            s3 += x1.w; t3 = fmaf(x1.w, x1.w, t3);
            s0 += x2.x; t0 = fmaf(x2.x, x2.x, t0);
            s1 += x2.y; t1 = fmaf(x2.y, x2.y, t1);
            s2 += x2.z; t2 = fmaf(x2.z, x2.z, t2);
            s3 += x2.w; t3 = fmaf(x2.w, x2.w, t3);
            s0 += x3.x; t0 = fmaf(x3.x, x3.x, t0);
            s1 += x3.y; t1 = fmaf(x3.y, x3.y, t1);
            s2 += x3.z; t2 = fmaf(x3.z, x3.z, t2);
            s3 += x3.w; t3 = fmaf(x3.w, x3.w, t3);
        }
        for (; p <= pend; p += STEP, ptr += dstep) {
            float4 x = __ldcs((const float4*)ptr);
            s0 += x.x; t0 = fmaf(x.x, x.x, t0);
            s1 += x.y; t1 = fmaf(x.y, x.y, t1);
            s2 += x.z; t2 = fmaf(x.z, x.z, t2);
            s3 += x.w; t3 = fmaf(x.w, x.w, t3);
        }
    }
    // retire A into smem (slot owner = (slotA, rs); rs=0 writes, rs=1 adds)
    if (rs == 0) {
        psum[slotA][0] = s0; psum[slotA][1] = t0;
        psum[slotA][2] = s1; psum[slotA][3] = t1;
        psum[slotA][4] = s2; psum[slotA][5] = t2;
        psum[slotA][6] = s3; psum[slotA][7] = t3;
    }
    __syncthreads();
    if (rs == 1) {
        psum[slotA][0] += s0; psum[slotA][1] += t0;
        psum[slotA][2] += s1; psum[slotA][3] += t1;
        psum[slotA][4] += s2; psum[slotA][5] += t2;
        psum[slotA][6] += s3; psum[slotA][7] += t3;
    }

    // ================= Phase B: rows p ≡ (q+3) mod 4, cols p+jB =================
    s0 = s1 = s2 = s3 = t0 = t1 = t2 = t3 = 0.f;
    {
        int p = ((q + 3) & 3) + 4 * rst;
        const int pend = 508 - jB;                  // per-thread exact bound
        const float* ptr = M + (size_t)p * (NN + 1) + jB;
        const ptrdiff_t dstep = (ptrdiff_t)STEP * (NN + 1);
        for (; p + 3 * STEP <= pend; p += 4 * STEP, ptr += 4 * dstep) {
            float4 x0 = __ldcs((const float4*)(ptr));
            float4 x1 = __ldcs((const float4*)(ptr + dstep));
            float4 x2 = __ldcs((const float4*)(ptr + 2 * dstep));
            float4 x3 = __ldcs((const float4*)(ptr + 3 * dstep));
            s0 += x0.x; t0 = fmaf(x0.x, x0.x, t0);
            s1 += x0.y; t1 = fmaf(x0.y, x0.y, t1);
            s2 += x0.z; t2 = fmaf(x0.z, x0.z, t2);
            s3 += x0.w; t3 = fmaf(x0.w, x0.w, t3);
            s0 += x1.x; t0 = fmaf(x1.x, x1.x, t0);
            s1 += x1.y; t1 = fmaf(x1.y, x1.y, t1);
            s2 += x1.z; t2 = fmaf(x1.z, x1.z, t2);
            s3 += x1.w; t3 = fmaf(x1.w, x1.w, t3);
            s0 += x2.x; t0 = fmaf(x2.x, x2.x, t0);
            s1 += x2.y; t1 = fmaf(x2.y, x2.y, t1);
            s2 += x2.z; t2 = fmaf(x2.z, x2.z, t2);
            s3 += x2.w; t3 = fmaf(x2.w, x2.w, t3);
            s0 += x3.x; t0 = fmaf(x3.x, x3.x, t0);
            s1 += x3.y; t1 = fmaf(x3.y, x3.y, t1);
            s2 += x3.z; t2 = fmaf(x3.z, x3.z, t2);
            s3 += x3.w; t3 = fmaf(x3.w, x3.w, t3);
        }
        for (; p <= pend; p += STEP, ptr += dstep) {
            float4 x = __ldcs((const float4*)ptr);
            s0 += x.x; t0 = fmaf(x.x, x.x, t0);
            s1 += x.y; t1 = fmaf(x.y, x.y, t1);
            s2 += x.z; t2 = fmaf(x.z, x.z, t2);
            s3 += x.w; t3 = fmaf(x.w, x.w, t3);
        }
    }
    __syncthreads();            // A-phase adds done before B writes same array? (disjoint slots, but keep ordering cheap)
    if (rs == 0) {
        psum[slotB][0] = s0; psum[slotB][1] = t0;
        psum[slotB][2] = s1; psum[slotB][3] = t1;
        psum[slotB][4] = s2; psum[slotB][5] = t2;
        psum[slotB][6] = s3; psum[slotB][7] = t3;
    }
    __syncthreads();
    if (rs == 1) {
        psum[slotB][0] += s0; psum[slotB][1] += t0;
        psum[slotB][2] += s1; psum[slotB][3] += t1;
        psum[slotB][4] += s2; psum[slotB][5] += t2;
        psum[slotB][6] += s3; psum[slotB][7] += t3;
    }
    __syncthreads();

    // ---- per-diag CTA partial: diag k <- (j=k+1-e, e), slot=k+3-e
    if (tid < KD) {
        float Ss = 0.f, Qs = 0.f;
        #pragma unroll
        for (int e = 0; e < 4; ++e) {
            int slot = tid + 3 - e;
            if (slot <= 511) { Ss += psum[slot][2*e]; Qs += psum[slot][2*e+1]; }
        }
        g_part[(b * RSG + rsg) * 512 + tid] = make_float2(Ss, Qs);
    }
    __threadfence();
    __syncthreads();

    __shared__ int is_last;
    if (tid == 0) {
        int old = atomicAdd(&g_count[b], 1);
        is_last = (old == RSG - 1);
        if (old == RSG - 1) g_count[b] = 0;   // reset for next graph replay
    }
    __syncthreads();

    if (is_last) {
        float contrib = 0.f;
        if (tid < KD) {
            float Ss = 0.f, Qs = 0.f;
            #pragma unroll
            for (int i = 0; i < RSG; ++i) {            // fixed order: deterministic
                float2 v = g_part[(b * RSG + i) * 512 + tid];
                Ss += v.x; Qs += v.y;
            }
            const float len = 511.0f - (float)tid;
            float mean = Ss / len;
            float var  = fmaxf((Qs - Ss * mean) / (len - 1.0f), 0.0f);
            contrib = sqrtf(var) * len * 0.2f;
        }
        __shared__ float red[TPB];
        red[tid] = contrib;
        __syncthreads();
        #pragma unroll
        for (int s = TPB / 2; s >= 32; s >>= 1) {
            if (tid < s) red[tid] += red[tid + s];
            __syncthreads();
        }
        if (tid < 32) {
            float v = red[tid];
            #pragma unroll
            for (int off = 16; off > 0; off >>= 1)
                v += __shfl_down_sync(0xFFFFFFFFu, v, off);
            if (tid == 0) {
                float loss = v / (float)KD;
                out[b] = loss;
                if (out_size >= 2 * B) out[B + b] = loss;
            }
        }
    }
}

extern "C" void kernel_launch(void* const* d_in, const int* in_sizes, int n_in,
                              void* d_out, int out_size) {
    const float* S = (const float*)d_in[0];
    float* out = (float*)d_out;
    const int B = in_sizes[0] / (NN * NN);
    dim3 grid(B, RSG);
    diag_quad<<<grid, TPB>>>(S, out, B, out_size);
}

// round 14
// speedup vs baseline: 1.1926x; 1.1926x over previous
#include <cuda_runtime.h>
#include <cuda_bf16.h>
#include <cstdint>

// B=128, N=512, diagonals k=0..509 (offset k+1), len(k)=511-k.
// out = (loss[B], loss[B]).
//
// cp.async-staged streaming: CTA (b, s) owns rows p ≡ s (mod 4) of batch b.
// Row p's segment cols [(p+1)&~3, 512) is staged to smem via cp.async.cg 16B
// (LDGSTS: latency decoupled from registers), double-buffered in 8-row tiles.
// Thread k owns diagonal k and reads buf[row][k+p+1] (consecutive threads ->
// consecutive smem addrs: conflict-free), accumulating sum/sumsq in 2 regs.
#define NN   512
#define KD   510
#define TPB  512
#define RSG  4          // strips per batch (rows interleaved mod 4)
#define SUB  8          // rows per pipeline tile
#define NT   16         // tiles per strip (128 rows)
#define MAXB 256

__device__ float2 g_part[MAXB * RSG * 512];
__device__ int    g_count[MAXB];     // zero-init; reset by last CTA each replay

__global__ __launch_bounds__(TPB, 4)
void diag_stream(const float* __restrict__ S, float* __restrict__ out,
                 int B, int out_size) {
    __shared__ float buf[2 * SUB * NN];    // 32 KB double buffer
    const int b    = blockIdx.x;
    const int s    = blockIdx.y;
    const int tid  = threadIdx.x;
    const int lane = tid & 31;
    const int w    = tid >> 5;      // 0..15
    const int wr   = w & 7;         // row-in-tile this warp loads
    const int half = w >> 3;        // chunk-half
    const int k    = tid;           // diagonal owned (k<510 valid)

    const float* __restrict__ M = S + (size_t)b * NN * NN;
    const uint32_t sbase = (uint32_t)__cvta_generic_to_shared(buf);

    float sk = 0.f, qk = 0.f;

    // ---- stage tile j into buffer (j&1): rows p = s + 4*(8j + 0..7)
    auto issue = [&](int j) {
        const int p  = s + RSG * (SUB * j + wr);          // < 512 always
        const int a4 = ((p + 1) & ~3) >> 2;               // first 16B chunk
        const float*  row  = M + (size_t)p * NN;
        const uint32_t drow = sbase + (uint32_t)(((j & 1) * SUB + wr) * NN) * 4u;
        #pragma unroll
        for (int i = 0; i < 2; ++i) {
            const int ch = a4 + lane + 32 * (2 * half + i);
            if (ch < NN / 4) {
                const uint32_t dst = drow + (uint32_t)ch * 16u;
                asm volatile("cp.async.cg.shared.global [%0], [%1], 16;"
                             :: "r"(dst), "l"(row + ch * 4) : "memory");
            }
        }
    };

    issue(0);
    asm volatile("cp.async.commit_group;" ::: "memory");

    for (int j = 0; j < NT; ++j) {
        if (j + 1 < NT) {
            issue(j + 1);
            asm volatile("cp.async.commit_group;" ::: "memory");
            asm volatile("cp.async.wait_group 1;" ::: "memory");
        } else {
            asm volatile("cp.async.wait_group 0;" ::: "memory");
        }
        __syncthreads();                       // tile j visible to all

        const float* tb = buf + (j & 1) * SUB * NN;
        const int p0 = s + RSG * SUB * j;
        #pragma unroll
        for (int rr = 0; rr < SUB; ++rr) {
            const int c = k + p0 + RSG * rr + 1;   // column on diag k at this row
            if (c < NN) {
                float x = tb[rr * NN + c];
                sk += x; qk = fmaf(x, x, qk);
            }
        }
        __syncthreads();                       // done with buffer before reuse
    }

    // ---- per-(strip,diag) partial
    if (k < KD)
        g_part[(b * RSG + s) * 512 + k] = make_float2(sk, qk);
    __threadfence();
    __syncthreads();

    __shared__ int is_last;
    if (tid == 0) {
        int old = atomicAdd(&g_count[b], 1);
        is_last = (old == RSG - 1);
        if (old == RSG - 1) g_count[b] = 0;    // reset for next graph replay
    }
    __syncthreads();

    if (is_last) {
        float contrib = 0.f;
        if (k < KD) {
            float Ss = 0.f, Qs = 0.f;
            #pragma unroll
            for (int i = 0; i < RSG; ++i) {    // fixed order: deterministic
                float2 v = g_part[(b * RSG + i) * 512 + k];
                Ss += v.x; Qs += v.y;
            }
            const float len = 511.0f - (float)k;
            float mean = Ss / len;
            float var  = fmaxf((Qs - Ss * mean) / (len - 1.0f), 0.0f);
            contrib = sqrtf(var) * len * 0.2f;
        }
        __shared__ float red[TPB];
        red[tid] = contrib;
        __syncthreads();
        #pragma unroll
        for (int st = TPB / 2; st >= 32; st >>= 1) {
            if (tid < st) red[tid] += red[tid + st];
            __syncthreads();
        }
        if (tid < 32) {
            float v = red[tid];
            #pragma unroll
            for (int off = 16; off > 0; off >>= 1)
                v += __shfl_down_sync(0xFFFFFFFFu, v, off);
            if (tid == 0) {
                float loss = v / (float)KD;
                out[b] = loss;
                if (out_size >= 2 * B) out[B + b] = loss;
            }
        }
    }
}

extern "C" void kernel_launch(void* const* d_in, const int* in_sizes, int n_in,
                              void* d_out, int out_size) {
    const float* S = (const float*)d_in[0];
    float* out = (float*)d_out;
    const int B = in_sizes[0] / (NN * NN);
    dim3 grid(B, RSG);
    diag_stream<<<grid, TPB>>>(S, out, B, out_size);
}